// round 13
// baseline (speedup 1.0000x reference)
#include <cuda_runtime.h>

#define Bv 16
#define Cv 512
#define Nv 9216
#define Kv 32
#define TN 512
#define NT (Nv / TN)      // 18 n-tiles for k_assign

#define SL 8              // k_agg n-slices (blocks per b)
#define NSL (Nv / SL)     // 1152 n per slice
#define CH2 32            // n per staged chunk
#define NCH2 (NSL / CH2)  // 36 chunks
#define XP2 1028          // x-dup tile pitch in words (16B-aligned rows, bank-spread)
#define AP 36             // aw tile pitch in words (16B-aligned, bank-spread)

// scratch (no cudaMalloc allowed)
__device__ __align__(16) float g_aw[(size_t)Bv * Nv * Kv];     // 18.9 MB aw[b][n][k]
__device__ float g_sawp[Bv * NT * Kv];                         // per-tile partial sums of aw
__device__ __align__(16) float g_part[(size_t)SL * Bv * Kv * Cv];  // 8.4 MB partial enc

typedef unsigned long long u64;

__device__ __forceinline__ u64 pack2(float lo, float hi) {
    u64 r; asm("mov.b64 %0,{%1,%2};" : "=l"(r) : "f"(lo), "f"(hi)); return r;
}
__device__ __forceinline__ void unpack2(u64 v, float& lo, float& hi) {
    asm("mov.b64 {%0,%1},%2;" : "=f"(lo), "=f"(hi) : "l"(v));
}
// packed fp32x2 FMA (FFMA2) — PTX-only, 2x FFMA throughput on sm_103a
__device__ __forceinline__ u64 ffma2(u64 a, u64 b, u64 c) {
    u64 d; asm("fma.rn.f32x2 %0,%1,%2,%3;" : "=l"(d) : "l"(a), "l"(b), "l"(c)); return d;
}
__device__ __forceinline__ unsigned smem_u32(const void* p) {
    unsigned r;
    asm("{ .reg .u64 t; cvta.to.shared.u64 t, %1; cvt.u32.u64 %0, t; }" : "=r"(r) : "l"(p));
    return r;
}
__device__ __forceinline__ void cp16(unsigned dst, const void* src) {
    asm volatile("cp.async.ca.shared.global [%0], [%1], 16;" :: "r"(dst), "l"(src));
}
#define CP_COMMIT() asm volatile("cp.async.commit_group;" ::: "memory")
#define CP_WAIT(N)  asm volatile("cp.async.wait_group %0;" :: "n"(N) : "memory")

// store (v, v) as one 8-byte shared store — builds the x-dup tile without packs
__device__ __forceinline__ void sts_dup(unsigned addr, float v) {
    asm volatile("st.shared.v2.f32 [%0], {%1, %1};" :: "r"(addr), "f"(v));
}
// 16B shared load as two u64 (two packed f32x2 operands)
__device__ __forceinline__ void lds_u64x2(u64& a, u64& b, unsigned addr) {
    asm volatile("ld.shared.v2.u64 {%0,%1}, [%2];" : "=l"(a), "=l"(b) : "r"(addr));
}

// ---------------------------------------------------------------------------
// Kernel 1: per (b, 512-n tile): logits via scaled L2, softmax over K=32,
// write aw, write deterministic per-tile sum_aw partials.
// (unchanged — known ~134 us)
// ---------------------------------------------------------------------------
__global__ void __launch_bounds__(256, 2) k_assign(
    const float* __restrict__ x, const float* __restrict__ cw,
    const float* __restrict__ scale)
{
    extern __shared__ float cwT[];                 // [Cv][Kv] = 64 KB, reused for reduction
    __shared__ float s_scale[Kv], s_sc2[Kv];
    const int tid = threadIdx.x;
    const int b   = blockIdx.y;
    const int n0  = blockIdx.x * TN;

    for (int i = tid; i < Cv * Kv; i += 256) {
        int k = i & 31, c = i >> 5;
        cwT[c * Kv + k] = cw[k * Cv + c];
    }
    __syncthreads();
    if (tid < Kv) {
        float s2 = 0.0f;
        #pragma unroll 8
        for (int c = 0; c < Cv; c++) { float v = cwT[c * Kv + tid]; s2 = fmaf(v, v, s2); }
        float sk = scale[tid];
        s_scale[tid] = sk;
        s_sc2[tid]   = sk * s2;
    }
    __syncthreads();

    const float* xb = x + (size_t)b * Cv * Nv + n0 + 2 * tid;

    u64 acc0[16], acc1[16];
    #pragma unroll
    for (int p = 0; p < 16; p++) { acc0[p] = 0ull; acc1[p] = 0ull; }
    u64 x2p = 0ull;

    float2 buf[8];
    #pragma unroll
    for (int i = 0; i < 8; i++) buf[i] = *reinterpret_cast<const float2*>(xb + (size_t)i * Nv);

    for (int c0 = 0; c0 < Cv; c0 += 8) {
        #pragma unroll
        for (int i = 0; i < 8; i++) {
            float2 xv = buf[i];
            int cn = c0 + 8 + i; cn = (cn < Cv) ? cn : 0;
            buf[i] = *reinterpret_cast<const float2*>(xb + (size_t)cn * Nv);

            u64 xp = pack2(xv.x, xv.y);
            x2p = ffma2(xp, xp, x2p);
            u64 d0 = pack2(xv.x, xv.x);
            u64 d1 = pack2(xv.y, xv.y);
            const ulonglong2* row = reinterpret_cast<const ulonglong2*>(cwT + (c0 + i) * Kv);
            #pragma unroll
            for (int q = 0; q < 8; q++) {
                ulonglong2 w = row[q];
                acc0[2 * q]     = ffma2(d0, w.x, acc0[2 * q]);
                acc1[2 * q]     = ffma2(d1, w.x, acc1[2 * q]);
                acc0[2 * q + 1] = ffma2(d0, w.y, acc0[2 * q + 1]);
                acc1[2 * q + 1] = ffma2(d1, w.y, acc1[2 * q + 1]);
            }
        }
    }

    float xcA[Kv], xcB[Kv], x2A, x2B;
    #pragma unroll
    for (int p = 0; p < 16; p++) {
        unpack2(acc0[p], xcA[2 * p], xcA[2 * p + 1]);
        unpack2(acc1[p], xcB[2 * p], xcB[2 * p + 1]);
    }
    unpack2(x2p, x2A, x2B);

    float* awout = g_aw + ((size_t)b * Nv + n0 + 2 * tid) * Kv;

    {
        float m = -1e30f;
        #pragma unroll
        for (int k = 0; k < Kv; k++) {
            float v = fmaf(s_scale[k], x2A - 2.0f * xcA[k], s_sc2[k]);
            xcA[k] = v; m = fmaxf(m, v);
        }
        float s = 0.0f;
        #pragma unroll
        for (int k = 0; k < Kv; k++) { float e = __expf(xcA[k] - m); xcA[k] = e; s += e; }
        float r = 1.0f / s;
        #pragma unroll
        for (int k = 0; k < Kv; k++) xcA[k] *= r;
        #pragma unroll
        for (int q = 0; q < 8; q++)
            reinterpret_cast<float4*>(awout)[q] =
                make_float4(xcA[4 * q], xcA[4 * q + 1], xcA[4 * q + 2], xcA[4 * q + 3]);
    }
    {
        float m = -1e30f;
        #pragma unroll
        for (int k = 0; k < Kv; k++) {
            float v = fmaf(s_scale[k], x2B - 2.0f * xcB[k], s_sc2[k]);
            xcB[k] = v; m = fmaxf(m, v);
        }
        float s = 0.0f;
        #pragma unroll
        for (int k = 0; k < Kv; k++) { float e = __expf(xcB[k] - m); xcB[k] = e; s += e; }
        float r = 1.0f / s;
        #pragma unroll
        for (int k = 0; k < Kv; k++) xcB[k] *= r;
        #pragma unroll
        for (int q = 0; q < 8; q++)
            reinterpret_cast<float4*>(awout + Kv)[q] =
                make_float4(xcB[4 * q], xcB[4 * q + 1], xcB[4 * q + 2], xcB[4 * q + 3]);
    }

    __syncthreads();
    float* red = cwT;                              // [256][33]
    #pragma unroll
    for (int k = 0; k < Kv; k++) red[tid * 33 + k] = xcA[k] + xcB[k];
    __syncthreads();
    if (tid < Kv) {
        float s = 0.0f;
        #pragma unroll 8
        for (int t = 0; t < 256; t++) s += red[t * 33 + tid];
        g_sawp[(b * NT + blockIdx.x) * Kv + tid] = s;
    }
}

// ---------------------------------------------------------------------------
// Kernel 2 (rebuilt): partial enc[k][c] = sum_n aw[n][k] * x[c][n] over one
// n-slice. Block = (b, slice): 256 threads cover the FULL 32k x 512c tile.
// Thread (kg = tid&3, cg = tid>>2) owns an 8k x 8c register tile
// (32 f32x2 accs). Per n: 2 LDS.128 give aw (k,k+1) pairs, 4 LDS.128 give
// duplicated (c,c) x pairs — 6 LDS.128 + 32 FFMA2, ZERO pack instructions.
// x is transposed+duplicated into smem via an LDG.128 -> STS.64{v,v}
// register pipeline (latency hidden under chunk compute); aw double-buffered
// via cp.async. 141 KB smem, 1 CTA/SM, grid 8x16 = single wave.
// ---------------------------------------------------------------------------
__global__ void __launch_bounds__(256, 1) k_agg(
    const float* __restrict__ x, float* __restrict__ part)
{
    extern __shared__ float sm[];
    float* xs  = sm;                       // [CH2][XP2] = 32 x 1028 words = 131.6 KB
    float* aw2 = sm + CH2 * XP2;           // [2][CH2][AP] = 9.2 KB
    const unsigned xs_u  = smem_u32(xs);
    const unsigned aw_u  = smem_u32(aw2);

    const int tid = threadIdx.x;
    const int b   = blockIdx.y;
    const int sl  = blockIdx.x;
    const int kg  = tid & 3;               // k-group: k = kg*8 .. kg*8+7
    const int cg  = tid >> 2;              // c-group: c = cg*8 .. cg*8+7
    const int nst = sl * NSL;

    const float* xb  = x + (size_t)b * Cv * Nv;          // full 512-c rows
    const float* awb = g_aw + ((size_t)b * Nv + nst) * Kv;

    u64 acc[4][8];
    #pragma unroll
    for (int p = 0; p < 4; p++)
        #pragma unroll
        for (int i = 0; i < 8; i++) acc[p][i] = 0ull;

    // staging descriptors: thread transposes rows c = tid and tid+256
    const int ca = tid, cb2 = tid + 256;
    const unsigned sta = xs_u + (unsigned)(2 * ca) * 4;   // + n_local*XP2*4
    const unsigned stb = xs_u + (unsigned)(2 * cb2) * 4;
    // aw staging: one cp16 per thread per chunk
    const int awn = tid >> 3, awk4 = tid & 7;
    const unsigned awdst = aw_u + (unsigned)(awn * AP + awk4 * 4) * 4;

    float4 xr[2][8];
    // prologue: LDG chunk 0 into regs, cp.async aw chunk 0 into buf 0
    #pragma unroll
    for (int j = 0; j < 8; j++) {
        xr[0][j] = *reinterpret_cast<const float4*>(xb + (size_t)ca  * Nv + nst + 4 * j);
        xr[1][j] = *reinterpret_cast<const float4*>(xb + (size_t)cb2 * Nv + nst + 4 * j);
    }
    cp16(awdst, awb + (size_t)awn * Kv + awk4 * 4);
    CP_COMMIT();

    // compute-loop operand bases
    const unsigned aw_rd = aw_u + (unsigned)(kg * 8) * 4;         // + (buf*CH2+n)*AP*4
    const unsigned xs_rd = xs_u + (unsigned)(16 * cg) * 4;        // + n*XP2*4

    for (int t = 0; t < NCH2; t++) {
        __syncthreads();                   // xs free (previous chunk's compute done)
        // STS chunk t (transpose + duplicate)
        #pragma unroll
        for (int j = 0; j < 8; j++) {
            sts_dup(sta + (unsigned)((4 * j + 0) * XP2) * 4, xr[0][j].x);
            sts_dup(sta + (unsigned)((4 * j + 1) * XP2) * 4, xr[0][j].y);
            sts_dup(sta + (unsigned)((4 * j + 2) * XP2) * 4, xr[0][j].z);
            sts_dup(sta + (unsigned)((4 * j + 3) * XP2) * 4, xr[0][j].w);
            sts_dup(stb + (unsigned)((4 * j + 0) * XP2) * 4, xr[1][j].x);
            sts_dup(stb + (unsigned)((4 * j + 1) * XP2) * 4, xr[1][j].y);
            sts_dup(stb + (unsigned)((4 * j + 2) * XP2) * 4, xr[1][j].z);
            sts_dup(stb + (unsigned)((4 * j + 3) * XP2) * 4, xr[1][j].w);
        }
        // LDG chunk t+1 (latency hidden under compute below)
        if (t + 1 < NCH2) {
            const int n0 = nst + (t + 1) * CH2;
            #pragma unroll
            for (int j = 0; j < 8; j++) {
                xr[0][j] = *reinterpret_cast<const float4*>(xb + (size_t)ca  * Nv + n0 + 4 * j);
                xr[1][j] = *reinterpret_cast<const float4*>(xb + (size_t)cb2 * Nv + n0 + 4 * j);
            }
            // aw prefetch t+1 into buf (t+1)&1
            cp16(awdst + (unsigned)(((t + 1) & 1) * CH2 * AP) * 4,
                 awb + (size_t)((t + 1) * CH2 + awn) * Kv + awk4 * 4);
            CP_COMMIT();
            CP_WAIT(1);                    // aw chunk t ready
        } else {
            CP_WAIT(0);
        }
        __syncthreads();                   // xs + aw chunk t visible

        // compute chunk t: 32 n, 6 LDS.128 + 32 FFMA2 per n
        const unsigned abase = aw_rd + (unsigned)((t & 1) * CH2 * AP) * 4;
        #pragma unroll 4
        for (int n = 0; n < CH2; n++) {
            u64 a01, a23, a45, a67;
            lds_u64x2(a01, a23, abase + (unsigned)(n * AP) * 4);
            lds_u64x2(a45, a67, abase + (unsigned)(n * AP) * 4 + 16);
            u64 xd[8];
            const unsigned xrow = xs_rd + (unsigned)(n * XP2) * 4;
            lds_u64x2(xd[0], xd[1], xrow);
            lds_u64x2(xd[2], xd[3], xrow + 16);
            lds_u64x2(xd[4], xd[5], xrow + 32);
            lds_u64x2(xd[6], xd[7], xrow + 48);
            #pragma unroll
            for (int i = 0; i < 8; i++) {
                acc[0][i] = ffma2(a01, xd[i], acc[0][i]);
                acc[1][i] = ffma2(a23, xd[i], acc[1][i]);
                acc[2][i] = ffma2(a45, xd[i], acc[2][i]);
                acc[3][i] = ffma2(a67, xd[i], acc[3][i]);
            }
        }
    }

    // write 8k x 8c partial tile: k-major rows, float4 stores
    float r[8][8];
    #pragma unroll
    for (int p = 0; p < 4; p++)
        #pragma unroll
        for (int i = 0; i < 8; i++)
            unpack2(acc[p][i], r[2 * p][i], r[2 * p + 1][i]);

    float* pout = part + (((size_t)sl * Bv + b) * Kv + kg * 8) * Cv + cg * 8;
    #pragma unroll
    for (int kk = 0; kk < 8; kk++) {
        reinterpret_cast<float4*>(pout + (size_t)kk * Cv)[0] =
            make_float4(r[kk][0], r[kk][1], r[kk][2], r[kk][3]);
        reinterpret_cast<float4*>(pout + (size_t)kk * Cv)[1] =
            make_float4(r[kk][4], r[kk][5], r[kk][6], r[kk][7]);
    }
}

// ---------------------------------------------------------------------------
// Kernel 3: out[b][k][c] = sum_s part[s][b][k][c] - sum_aw[b][k] * cw[k][c]
// Block = one (b, k) pair; 256 threads x float2 covers c = 512.
// ---------------------------------------------------------------------------
__global__ void __launch_bounds__(256) k_fin(
    const float* __restrict__ cw, float* __restrict__ out)
{
    __shared__ float ssum;
    const int bx = blockIdx.x;             // 0..511
    const int b = bx >> 5, k = bx & 31;
    const int tid = threadIdx.x;

    if (tid == 0) {
        float s = 0.0f;
        #pragma unroll
        for (int t = 0; t < NT; t++) s += g_sawp[(b * NT + t) * Kv + k];
        ssum = s;
    }
    __syncthreads();

    float2 v = make_float2(0.0f, 0.0f);
    #pragma unroll
    for (int s = 0; s < SL; s++) {
        float2 p = reinterpret_cast<const float2*>(
            g_part + (((size_t)s * Bv + b) * Kv + k) * Cv)[tid];
        v.x += p.x; v.y += p.y;
    }
    float2 cwv = reinterpret_cast<const float2*>(cw + (size_t)k * Cv)[tid];
    float sv = ssum;
    float2 o;
    o.x = v.x - sv * cwv.x;
    o.y = v.y - sv * cwv.y;
    reinterpret_cast<float2*>(out + ((size_t)b * Kv + k) * Cv)[tid] = o;
}

extern "C" void kernel_launch(void* const* d_in, const int* in_sizes, int n_in,
                              void* d_out, int out_size)
{
    const float* x  = (const float*)d_in[0];   // (B, C, H, W)
    const float* cw = (const float*)d_in[1];   // (K, C)
    const float* sc = (const float*)d_in[2];   // (K,)
    float* out = (float*)d_out;                // (B, K, C)

    static int inited = 0;
    if (!inited) {
        cudaFuncSetAttribute(k_assign, cudaFuncAttributeMaxDynamicSharedMemorySize, Cv * Kv * 4);
        cudaFuncSetAttribute(k_agg, cudaFuncAttributeMaxDynamicSharedMemorySize,
                             (CH2 * XP2 + 2 * CH2 * AP) * 4);
        inited = 1;
    }

    float* part;
    cudaGetSymbolAddress((void**)&part, g_part);   // no alloc; capture-safe

    k_assign<<<dim3(NT, Bv), 256, Cv * Kv * 4>>>(x, cw, sc);
    k_agg<<<dim3(SL, Bv), 256, (CH2 * XP2 + 2 * CH2 * AP) * 4>>>(x, part);
    k_fin<<<Bv * Kv, 256>>>(cw, out);
}

// round 14
// speedup vs baseline: 1.2898x; 1.2898x over previous
#include <cuda_runtime.h>

#define Bv 16
#define Cv 512
#define Nv 9216
#define Kv 32
#define TN 512
#define NT (Nv / TN)      // 18 n-tiles for k_assign

#define SL 8              // k_agg n-slices per (b, c-half)
#define NSL (Nv / SL)     // 1152 n per slice
#define CHN 32            // n per staged chunk
#define NCH (NSL / CHN)   // 36 chunks
#define CHC 256           // c per block (c-half)
#define XP 36             // x tile pitch (words) — conflict-free B-frag reads
#define AP 40             // aw tile pitch (words) — conflict-free A-frag reads

// scratch (no cudaMalloc allowed)
__device__ __align__(16) float g_aw[(size_t)Bv * Nv * Kv];        // 18.9 MB aw[b][n][k]
__device__ float g_sawp[Bv * NT * Kv];                            // per-tile sums of aw
__device__ __align__(16) float g_part[(size_t)SL * Bv * Kv * Cv]; // 8.4 MB partial enc

typedef unsigned long long u64;

__device__ __forceinline__ u64 pack2(float lo, float hi) {
    u64 r; asm("mov.b64 %0,{%1,%2};" : "=l"(r) : "f"(lo), "f"(hi)); return r;
}
__device__ __forceinline__ void unpack2(u64 v, float& lo, float& hi) {
    asm("mov.b64 {%0,%1},%2;" : "=f"(lo), "=f"(hi) : "l"(v));
}
__device__ __forceinline__ u64 ffma2(u64 a, u64 b, u64 c) {
    u64 d; asm("fma.rn.f32x2 %0,%1,%2,%3;" : "=l"(d) : "l"(a), "l"(b), "l"(c)); return d;
}
__device__ __forceinline__ unsigned smem_u32(const void* p) {
    unsigned r;
    asm("{ .reg .u64 t; cvta.to.shared.u64 t, %1; cvt.u32.u64 %0, t; }" : "=r"(r) : "l"(p));
    return r;
}
__device__ __forceinline__ void cp16(unsigned dst, const void* src) {
    asm volatile("cp.async.ca.shared.global [%0], [%1], 16;" :: "r"(dst), "l"(src));
}
#define CP_COMMIT() asm volatile("cp.async.commit_group;" ::: "memory")
#define CP_WAIT(N)  asm volatile("cp.async.wait_group %0;" :: "n"(N) : "memory")

// tf32 helpers: hi = rna-rounded tf32 bits (valid f32 pattern); lo = x - hi
__device__ __forceinline__ unsigned tf32_of(float x) {
    unsigned u; asm("cvt.rna.tf32.f32 %0, %1;" : "=r"(u) : "f"(x)); return u;
}

// m16n8k8 tf32 mma: D += A*B (A row-major, B col-major), fp32 accumulate
#define MMA8(d, a0, a1, a2, a3, b0, b1) \
    asm volatile("mma.sync.aligned.m16n8k8.row.col.f32.tf32.tf32.f32 " \
        "{%0,%1,%2,%3}, {%4,%5,%6,%7}, {%8,%9}, {%0,%1,%2,%3};" \
        : "+f"(d[0]), "+f"(d[1]), "+f"(d[2]), "+f"(d[3]) \
        : "r"(a0), "r"(a1), "r"(a2), "r"(a3), "r"(b0), "r"(b1))

// ---------------------------------------------------------------------------
// Kernel 1: unchanged (known ~135 us): logits via scaled L2, softmax K=32,
// write aw + deterministic per-tile sum_aw partials.
// ---------------------------------------------------------------------------
__global__ void __launch_bounds__(256, 2) k_assign(
    const float* __restrict__ x, const float* __restrict__ cw,
    const float* __restrict__ scale)
{
    extern __shared__ float cwT[];                 // [Cv][Kv] = 64 KB
    __shared__ float s_scale[Kv], s_sc2[Kv];
    const int tid = threadIdx.x;
    const int b   = blockIdx.y;
    const int n0  = blockIdx.x * TN;

    for (int i = tid; i < Cv * Kv; i += 256) {
        int k = i & 31, c = i >> 5;
        cwT[c * Kv + k] = cw[k * Cv + c];
    }
    __syncthreads();
    if (tid < Kv) {
        float s2 = 0.0f;
        #pragma unroll 8
        for (int c = 0; c < Cv; c++) { float v = cwT[c * Kv + tid]; s2 = fmaf(v, v, s2); }
        float sk = scale[tid];
        s_scale[tid] = sk;
        s_sc2[tid]   = sk * s2;
    }
    __syncthreads();

    const float* xb = x + (size_t)b * Cv * Nv + n0 + 2 * tid;

    u64 acc0[16], acc1[16];
    #pragma unroll
    for (int p = 0; p < 16; p++) { acc0[p] = 0ull; acc1[p] = 0ull; }
    u64 x2p = 0ull;

    float2 buf[8];
    #pragma unroll
    for (int i = 0; i < 8; i++) buf[i] = *reinterpret_cast<const float2*>(xb + (size_t)i * Nv);

    for (int c0 = 0; c0 < Cv; c0 += 8) {
        #pragma unroll
        for (int i = 0; i < 8; i++) {
            float2 xv = buf[i];
            int cn = c0 + 8 + i; cn = (cn < Cv) ? cn : 0;
            buf[i] = *reinterpret_cast<const float2*>(xb + (size_t)cn * Nv);

            u64 xp = pack2(xv.x, xv.y);
            x2p = ffma2(xp, xp, x2p);
            u64 d0 = pack2(xv.x, xv.x);
            u64 d1 = pack2(xv.y, xv.y);
            const ulonglong2* row = reinterpret_cast<const ulonglong2*>(cwT + (c0 + i) * Kv);
            #pragma unroll
            for (int q = 0; q < 8; q++) {
                ulonglong2 w = row[q];
                acc0[2 * q]     = ffma2(d0, w.x, acc0[2 * q]);
                acc1[2 * q]     = ffma2(d1, w.x, acc1[2 * q]);
                acc0[2 * q + 1] = ffma2(d0, w.y, acc0[2 * q + 1]);
                acc1[2 * q + 1] = ffma2(d1, w.y, acc1[2 * q + 1]);
            }
        }
    }

    float xcA[Kv], xcB[Kv], x2A, x2B;
    #pragma unroll
    for (int p = 0; p < 16; p++) {
        unpack2(acc0[p], xcA[2 * p], xcA[2 * p + 1]);
        unpack2(acc1[p], xcB[2 * p], xcB[2 * p + 1]);
    }
    unpack2(x2p, x2A, x2B);

    float* awout = g_aw + ((size_t)b * Nv + n0 + 2 * tid) * Kv;

    {
        float m = -1e30f;
        #pragma unroll
        for (int k = 0; k < Kv; k++) {
            float v = fmaf(s_scale[k], x2A - 2.0f * xcA[k], s_sc2[k]);
            xcA[k] = v; m = fmaxf(m, v);
        }
        float s = 0.0f;
        #pragma unroll
        for (int k = 0; k < Kv; k++) { float e = __expf(xcA[k] - m); xcA[k] = e; s += e; }
        float r = 1.0f / s;
        #pragma unroll
        for (int k = 0; k < Kv; k++) xcA[k] *= r;
        #pragma unroll
        for (int q = 0; q < 8; q++)
            reinterpret_cast<float4*>(awout)[q] =
                make_float4(xcA[4 * q], xcA[4 * q + 1], xcA[4 * q + 2], xcA[4 * q + 3]);
    }
    {
        float m = -1e30f;
        #pragma unroll
        for (int k = 0; k < Kv; k++) {
            float v = fmaf(s_scale[k], x2B - 2.0f * xcB[k], s_sc2[k]);
            xcB[k] = v; m = fmaxf(m, v);
        }
        float s = 0.0f;
        #pragma unroll
        for (int k = 0; k < Kv; k++) { float e = __expf(xcB[k] - m); xcB[k] = e; s += e; }
        float r = 1.0f / s;
        #pragma unroll
        for (int k = 0; k < Kv; k++) xcB[k] *= r;
        #pragma unroll
        for (int q = 0; q < 8; q++)
            reinterpret_cast<float4*>(awout + Kv)[q] =
                make_float4(xcB[4 * q], xcB[4 * q + 1], xcB[4 * q + 2], xcB[4 * q + 3]);
    }

    __syncthreads();
    float* red = cwT;                              // [256][33]
    #pragma unroll
    for (int k = 0; k < Kv; k++) red[tid * 33 + k] = xcA[k] + xcB[k];
    __syncthreads();
    if (tid < Kv) {
        float s = 0.0f;
        #pragma unroll 8
        for (int t = 0; t < 256; t++) s += red[t * 33 + tid];
        g_sawp[(b * NT + blockIdx.x) * Kv + tid] = s;
    }
}

// ---------------------------------------------------------------------------
// Kernel 2 (tensor cores): partial[k][c] = sum_n aw[n][k] * x[c][n] for one
// (b, c-half of 256, n-slice of 1152), via mma.sync m16n8k8 tf32 with 3xTF32
// split (hi*hi + lo*hi + hi*lo) -> fp32-grade accuracy.
// Block: 256 thr / 8 warps; warp = (k-half mh = w&1) x (c-quad cq = w>>1, 64c).
// Acc per warp: m16 x n64 = 8 frags x 4 f32 = 32 regs.
// Staging per 32-n chunk (cp.async, double-buffered):
//   x fp32 [256 c][32 n] pitch 36 (B col-major; conflict-free frag reads)
//   aw fp32 [32 n][32 k] pitch 40 (A row-major; conflict-free frag reads)
// tf32 hi/lo split happens in-register at fragment load.
// Grid (2 ch x 8 sl) x 16 b = 256 blocks, 2 CTAs/SM (84 KB smem each).
// ---------------------------------------------------------------------------
__global__ void __launch_bounds__(256, 2) k_agg(
    const float* __restrict__ x, float* __restrict__ part)
{
    extern __shared__ float sm[];
    float* xs  = sm;                       // [2][CHC][XP] = 73.7 KB
    float* as_ = sm + 2 * CHC * XP;        // [2][CHN][AP] = 10.2 KB
    const unsigned xs_u = smem_u32(xs);
    const unsigned as_u = smem_u32(as_);

    const int tid = threadIdx.x, w = tid >> 5, l = tid & 31;
    const int gid = l >> 2, tig = l & 3;   // mma group / thread-in-group
    const int b  = blockIdx.y;
    const int ch = blockIdx.x >> 3;        // c-half
    const int sl = blockIdx.x & 7;         // n-slice
    const int mh = w & 1;                  // k-half (16 rows)
    const int cq = w >> 1;                 // c-quad (64 cols)
    const int nst = sl * NSL;
    const int c0g = ch * CHC;

    const float* xb  = x + (size_t)b * Cv * Nv + (size_t)c0g * Nv;
    const float* awb = g_aw + ((size_t)b * Nv + nst) * Kv;

    float acc[8][4];
    #pragma unroll
    for (int ct = 0; ct < 8; ct++)
        #pragma unroll
        for (int i = 0; i < 4; i++) acc[ct][i] = 0.0f;

    // staging descriptors
    const unsigned xdst0 = xs_u + (unsigned)(tid * XP) * 4;          // + buf off
    const float*  xsrc0 = xb + (size_t)tid * Nv + nst;
    const int an = tid >> 3, ak4 = tid & 7;                          // aw: n, k-quad
    const unsigned adst0 = as_u + (unsigned)(an * AP + ak4 * 4) * 4;

    // ---- prologue: stage chunk 0 into buffer 0 ----
    #pragma unroll
    for (int j = 0; j < 8; j++) cp16(xdst0 + 16u * j, xsrc0 + 4 * j);
    cp16(adst0, awb + (size_t)an * Kv + ak4 * 4);
    CP_COMMIT();

    for (int t = 0; t < NCH; t++) {
        if (t + 1 < NCH) {
            const int sb = (t + 1) & 1;
            const int n0 = (t + 1) * CHN;
            #pragma unroll
            for (int j = 0; j < 8; j++)
                cp16(xdst0 + (unsigned)(sb * CHC * XP) * 4 + 16u * j, xsrc0 + n0 + 4 * j);
            cp16(adst0 + (unsigned)(sb * CHN * AP) * 4,
                 awb + (size_t)(n0 + an) * Kv + ak4 * 4);
            CP_COMMIT();
            CP_WAIT(1);                    // chunk t complete (t+1 in flight)
        } else {
            CP_WAIT(0);
        }
        __syncthreads();

        // compute chunk t
        const int sel = t & 1;
        const float* xb_s = xs  + sel * CHC * XP;
        const float* ab_s = as_ + sel * CHN * AP;
        #pragma unroll
        for (int s = 0; s < 4; s++) {      // kk-steps of 8 n
            // A fragment (aw): row m = k, col = n; split hi/lo
            unsigned ah[4], al[4];
            #pragma unroll
            for (int i = 0; i < 4; i++) {
                int nn = s * 8 + tig + ((i & 2) ? 4 : 0);
                int kk = mh * 16 + gid + ((i & 1) ? 8 : 0);
                float af = ab_s[nn * AP + kk];
                ah[i] = tf32_of(af);
                al[i] = tf32_of(af - __uint_as_float(ah[i]));
            }
            const float* xrow = xb_s + (size_t)(cq * 64 + gid) * XP + s * 8 + tig;
            #pragma unroll
            for (int ct = 0; ct < 8; ct++) {
                float bf0 = xrow[ct * 8 * XP];
                float bf1 = xrow[ct * 8 * XP + 4];
                unsigned bh0 = tf32_of(bf0), bh1 = tf32_of(bf1);
                unsigned bl0 = tf32_of(bf0 - __uint_as_float(bh0));
                unsigned bl1 = tf32_of(bf1 - __uint_as_float(bh1));
                MMA8(acc[ct], ah[0], ah[1], ah[2], ah[3], bh0, bh1);
                MMA8(acc[ct], al[0], al[1], al[2], al[3], bh0, bh1);
                MMA8(acc[ct], ah[0], ah[1], ah[2], ah[3], bl0, bl1);
            }
        }
        __syncthreads();                   // buffer free before restage
    }

    // epilogue: write 16k x 64c partial tile per warp
    float* pr = part + (((size_t)sl * Bv + b) * Kv + mh * 16) * Cv
                     + c0g + cq * 64;
    #pragma unroll
    for (int ct = 0; ct < 8; ct++) {
        int cc = ct * 8 + tig * 2;
        *reinterpret_cast<float2*>(pr + (size_t)gid * Cv + cc) =
            make_float2(acc[ct][0], acc[ct][1]);
        *reinterpret_cast<float2*>(pr + (size_t)(gid + 8) * Cv + cc) =
            make_float2(acc[ct][2], acc[ct][3]);
    }
}

// ---------------------------------------------------------------------------
// Kernel 3: out[b][k][c] = sum_s part[s][b][k][c] - sum_aw[b][k] * cw[k][c]
// ---------------------------------------------------------------------------
__global__ void __launch_bounds__(256) k_fin(
    const float* __restrict__ cw, float* __restrict__ out)
{
    __shared__ float ssum;
    const int bx = blockIdx.x;             // 0..511
    const int b = bx >> 5, k = bx & 31;
    const int tid = threadIdx.x;

    if (tid == 0) {
        float s = 0.0f;
        #pragma unroll
        for (int t = 0; t < NT; t++) s += g_sawp[(b * NT + t) * Kv + k];
        ssum = s;
    }
    __syncthreads();

    float2 v = make_float2(0.0f, 0.0f);
    #pragma unroll
    for (int s = 0; s < SL; s++) {
        float2 p = reinterpret_cast<const float2*>(
            g_part + (((size_t)s * Bv + b) * Kv + k) * Cv)[tid];
        v.x += p.x; v.y += p.y;
    }
    float2 cwv = reinterpret_cast<const float2*>(cw + (size_t)k * Cv)[tid];
    float sv = ssum;
    float2 o;
    o.x = v.x - sv * cwv.x;
    o.y = v.y - sv * cwv.y;
    reinterpret_cast<float2*>(out + ((size_t)b * Kv + k) * Cv)[tid] = o;
}

extern "C" void kernel_launch(void* const* d_in, const int* in_sizes, int n_in,
                              void* d_out, int out_size)
{
    const float* x  = (const float*)d_in[0];   // (B, C, H, W)
    const float* cw = (const float*)d_in[1];   // (K, C)
    const float* sc = (const float*)d_in[2];   // (K,)
    float* out = (float*)d_out;                // (B, K, C)

    static int inited = 0;
    if (!inited) {
        cudaFuncSetAttribute(k_assign, cudaFuncAttributeMaxDynamicSharedMemorySize, Cv * Kv * 4);
        cudaFuncSetAttribute(k_agg, cudaFuncAttributeMaxDynamicSharedMemorySize,
                             (2 * CHC * XP + 2 * CHN * AP) * 4);
        inited = 1;
    }

    float* part;
    cudaGetSymbolAddress((void**)&part, g_part);   // no alloc; capture-safe

    k_assign<<<dim3(NT, Bv), 256, Cv * Kv * 4>>>(x, cw, sc);
    k_agg<<<dim3(16, Bv), 256, (2 * CHC * XP + 2 * CHN * AP) * 4>>>(x, part);
    k_fin<<<Bv * Kv, 256>>>(cw, out);
}